// round 7
// baseline (speedup 1.0000x reference)
#include <cuda_runtime.h>
#include <math.h>

// Problem constants (fixed shapes from setup_inputs)
#define BI      8
#define SI      4
#define NPARTS  17
#define TAGD    1
#define CCH     ((1 + TAGD) * NPARTS)   // 34
#define HH      128
#define WW      128
#define HW      (HH * WW)               // 16384
#define NPERS   30
#define LTAG    (NPARTS * HW)           // 278528
#define EPSV    1e-6f

// pull/push blocks FIRST (overlap their latency-bound gathers with the stream)
#define PP_BLOCKS   (BI * SI)                          // 32
// Det term: one (b,p) plane = HW floats; 8 blocks/plane, thread does 2 float4
#define BLOCKS_PER_PLANE 8
#define DET_BLOCKS  (BI * NPARTS * BLOCKS_PER_PLANE)   // 1088
#define TOTAL_BLOCKS (DET_BLOCKS + PP_BLOCKS)          // 1120

// Per-block partials + completion counter (no device-side allocation allowed)
__device__ double g_scratch[TOTAL_BLOCKS];
__device__ unsigned int g_done = 0;   // reset by the last block each call

__global__ void __launch_bounds__(256, 3)
loss_fused_kernel(const float* __restrict__ preds,
                  const float* __restrict__ masks,
                  const float* __restrict__ heatmaps,
                  const int*   __restrict__ kp32,
                  float* __restrict__ out)
{
    const int bid = blockIdx.x;
    const int tid = threadIdx.x;
    const unsigned FULL = 0xffffffffu;

    __shared__ bool s_last;

    if (bid >= PP_BLOCKS) {
        // ---------------- det MSE partial ----------------
        const int det_bid = bid - PP_BLOCKS;
        const int plane = det_bid >> 3;                // / BLOCKS_PER_PLANE
        const int chunk = det_bid & (BLOCKS_PER_PLANE - 1);
        const int b = plane / NPARTS;
        const int p = plane % NPARTS;
        // Each chunk covers 2048 elements; thread handles hw0 and hw0+1024.
        const int hw0 = chunk * 2048 + tid * 4;
        const int hw1 = hw0 + 1024;

        const float* mb = masks    + (size_t)b * HW;
        const float* hb = heatmaps + ((size_t)b * NPARTS + p) * HW;
        const float* pb0 = preds + ((size_t)(b * SI + 0) * CCH + p) * HW;
        const float* pb1 = preds + ((size_t)(b * SI + 1) * CCH + p) * HW;
        const float* pb2 = preds + ((size_t)(b * SI + 2) * CCH + p) * HW;
        const float* pb3 = preds + ((size_t)(b * SI + 3) * CCH + p) * HW;

        // Issue ALL 12 LDG.128 before any compute -> high MLP_eff
        float4 ld[12];
        ld[0]  = *reinterpret_cast<const float4*>(mb  + hw0);
        ld[1]  = *reinterpret_cast<const float4*>(mb  + hw1);
        ld[2]  = *reinterpret_cast<const float4*>(hb  + hw0);
        ld[3]  = *reinterpret_cast<const float4*>(hb  + hw1);
        ld[4]  = *reinterpret_cast<const float4*>(pb0 + hw0);
        ld[5]  = *reinterpret_cast<const float4*>(pb0 + hw1);
        ld[6]  = *reinterpret_cast<const float4*>(pb1 + hw0);
        ld[7]  = *reinterpret_cast<const float4*>(pb1 + hw1);
        ld[8]  = *reinterpret_cast<const float4*>(pb2 + hw0);
        ld[9]  = *reinterpret_cast<const float4*>(pb2 + hw1);
        ld[10] = *reinterpret_cast<const float4*>(pb3 + hw0);
        ld[11] = *reinterpret_cast<const float4*>(pb3 + hw1);

        float acc = 0.0f;
#pragma unroll
        for (int s = 0; s < SI; s++) {
            const float4 pa = ld[4 + 2 * s];
            const float4 pbv = ld[5 + 2 * s];
            {
                const float dx = pa.x - ld[2].x, dy = pa.y - ld[2].y;
                const float dz = pa.z - ld[2].z, dw = pa.w - ld[2].w;
                acc += dx * dx * ld[0].x + dy * dy * ld[0].y + dz * dz * ld[0].z + dw * dw * ld[0].w;
            }
            {
                const float dx = pbv.x - ld[3].x, dy = pbv.y - ld[3].y;
                const float dz = pbv.z - ld[3].z, dw = pbv.w - ld[3].w;
                acc += dx * dx * ld[1].x + dy * dy * ld[1].y + dz * dz * ld[1].z + dw * dw * ld[1].w;
            }
        }

        // block reduction (8 warps)
#pragma unroll
        for (int o = 16; o > 0; o >>= 1) acc += __shfl_xor_sync(FULL, acc, o);
        __shared__ float wsum[8];
        const int wid = tid >> 5;
        if ((tid & 31) == 0) wsum[wid] = acc;
        __syncthreads();
        if (tid == 0) {
            float s = 0.0f;
#pragma unroll
            for (int w = 0; w < 8; w++) s += wsum[w];
            // pre-weighted: weight 1.0 * mean over (B,S,17,H,W)
            g_scratch[bid] = (double)s * (1.0 / ((double)BI * SI * NPARTS * HW));
        }
    } else {
        // ---------------- pull/push for one (b,s) ----------------
        const int bs = bid;
        const int b = bs / SI;
        const int s = bs % SI;

        __shared__ float gm[NPERS * NPARTS];   // g * vis
        __shared__ float vf[NPERS * NPARTS];   // vis as float
        __shared__ int   is64_s;

        // Detect keypoint dtype with one parallel warp pass:
        // int64 little-endian with values < 2^31 => all odd 32-bit words zero.
        if (tid < 32) {
            const int v = kp32[2 * tid + 1];   // odd words 1,3,...,63
            const unsigned nz = __ballot_sync(FULL, v != 0);
            if (tid == 0) is64_s = (nz == 0u) ? 1 : 0;
        }
        __syncthreads();
        const int is64 = is64_s;

        const float* tagbase = preds + ((size_t)(b * SI + s) * CCH + NPARTS) * HW;

        for (int i = tid; i < NPERS * NPARTS; i += blockDim.x) {
            const int p = i / NPARTS;
            const int k = i % NPARTS;
            const int e = (b * NPERS + p) * NPARTS + k;   // entry index
            int idx, visv;
            if (is64) { idx = kp32[4 * e];     visv = kp32[4 * e + 2]; }
            else      { idx = kp32[2 * e];     visv = kp32[2 * e + 1]; }
            const float v = (visv > 0) ? 1.0f : 0.0f;
            gm[i] = v * tagbase[idx];   // idx always in [0, LTAG)
            vf[i] = v;
        }
        __syncthreads();

        if (tid < 32) {
            const int p = tid;
            float cnt = 0.0f, sum = 0.0f;
            if (p < NPERS) {
#pragma unroll
                for (int k = 0; k < NPARTS; k++) {
                    cnt += vf[p * NPARTS + k];
                    sum += gm[p * NPARTS + k];
                }
            }
            const float validf = (p < NPERS && cnt > 0.0f) ? 1.0f : 0.0f;
            const float safe   = fmaxf(cnt, 1.0f);
            const float mean   = sum / safe;

            float pull_pp = 0.0f;
            if (p < NPERS) {
#pragma unroll
                for (int k = 0; k < NPARTS; k++) {
                    const float d = gm[p * NPARTS + k] - mean * vf[p * NPARTS + k];
                    pull_pp += d * d;
                }
            }
            pull_pp /= safe;   // TAG_DIM == 1

            const unsigned bal = __ballot_sync(FULL, validf > 0.0f);
            const float num = (float)__popc(bal);

            float pullv = pull_pp * validf;
#pragma unroll
            for (int o = 16; o > 0; o >>= 1) pullv += __shfl_xor_sync(FULL, pullv, o);
            const float pull_bs = pullv / (num + EPSV);

            float row = 0.0f;
            for (int q = 0; q < NPERS; q++) {
                const float mq = __shfl_sync(FULL, mean,   q);
                const float vq = __shfl_sync(FULL, validf, q);
                const float d  = mean - mq;
                row += vq * expf(-d * d);
            }
            row *= validf;
#pragma unroll
            for (int o = 16; o > 0; o >>= 1) row += __shfl_xor_sync(FULL, row, o);
            const float push_sum = row - num;
            const float push_bs  = push_sum / ((num - 1.0f) * num + EPSV) * 0.5f;

            if (tid == 0) {
                g_scratch[bid] = (double)(0.001f * (push_bs + pull_bs)) / (double)(BI * SI);
            }
        }
        __syncthreads();
    }

    // ------------- fenceless completion protocol (no CCTL.IVALL) -------------
    // tid0's scratch store is drained by the RELEASE atomic below; the last
    // block's tail loads are control-dependent on the returned count (in-order
    // issue => no load starts before the acquire completes) and use __ldcg.
    if (tid == 0) {
        unsigned prev;
        asm volatile("atom.acq_rel.gpu.global.add.u32 %0, [%1], 1;"
                     : "=r"(prev) : "l"(&g_done) : "memory");
        s_last = (prev == (unsigned)(TOTAL_BLOCKS - 1));
    }
    __syncthreads();

    if (s_last) {
        double acc = 0.0;
        // Fixed-order reduction -> deterministic regardless of which block runs it.
        for (int i = tid; i < TOTAL_BLOCKS; i += 256) {
            acc += __ldcg(&g_scratch[i]);
        }
#pragma unroll
        for (int o = 16; o > 0; o >>= 1) acc += __shfl_xor_sync(FULL, acc, o);
        __shared__ double wsum2[8];
        const int wid = tid >> 5;
        if ((tid & 31) == 0) wsum2[wid] = acc;
        __syncthreads();
        if (tid == 0) {
            double s = 0.0;
#pragma unroll
            for (int w = 0; w < 8; w++) s += wsum2[w];
            out[0] = (float)s;
            g_done = 0;   // all blocks arrived; safe plain store, visible next launch
        }
    }
}

extern "C" void kernel_launch(void* const* d_in, const int* in_sizes, int n_in,
                              void* d_out, int out_size)
{
    (void)out_size;
    const float* preds    = nullptr;
    const float* masks    = nullptr;
    const float* heatmaps = nullptr;
    const int*   kp       = nullptr;

    // Identify inputs by element count (defensive vs. ordering)
    for (int i = 0; i < n_in; i++) {
        switch (in_sizes[i]) {
            case BI * SI * CCH * HW:   preds    = (const float*)d_in[i]; break;  // 17825792
            case BI * HW:              masks    = (const float*)d_in[i]; break;  // 131072
            case BI * NPARTS * HW:     heatmaps = (const float*)d_in[i]; break;  // 2228224
            case BI * NPERS * NPARTS * 2: kp    = (const int*)d_in[i];   break;  // 8160
            default: break;
        }
    }
    if (!preds    && n_in > 0) preds    = (const float*)d_in[0];
    if (!masks    && n_in > 1) masks    = (const float*)d_in[1];
    if (!heatmaps && n_in > 2) heatmaps = (const float*)d_in[2];
    if (!kp       && n_in > 3) kp       = (const int*)d_in[3];

    loss_fused_kernel<<<TOTAL_BLOCKS, 256>>>(preds, masks, heatmaps, kp, (float*)d_out);
}

// round 8
// speedup vs baseline: 1.4700x; 1.4700x over previous
#include <cuda_runtime.h>
#include <math.h>

// Problem constants (fixed shapes from setup_inputs)
#define BI      8
#define SI      4
#define NPARTS  17
#define TAGD    1
#define CCH     ((1 + TAGD) * NPARTS)   // 34
#define HH      128
#define WW      128
#define HW      (HH * WW)               // 16384
#define NPERS   30
#define LTAG    (NPARTS * HW)           // 278528
#define EPSV    1e-6f

#define NTHREADS 512
// pull/push blocks FIRST (overlap their latency-bound gathers with the stream)
#define PP_BLOCKS   (BI * SI)                          // 32
// Det: one (b,p) plane = HW floats; 8 blocks/plane, 512 thr, 1 float4/thread/chunk
#define BLOCKS_PER_PLANE 8
#define DET_BLOCKS  (BI * NPARTS * BLOCKS_PER_PLANE)   // 1088
#define TOTAL_BLOCKS (DET_BLOCKS + PP_BLOCKS)          // 1120

// Per-block partials + completion counter (no device-side allocation allowed)
__device__ double g_scratch[TOTAL_BLOCKS];
__device__ unsigned int g_done = 0;   // reset by the last block each call

__global__ void __launch_bounds__(NTHREADS)
loss_fused_kernel(const float* __restrict__ preds,
                  const float* __restrict__ masks,
                  const float* __restrict__ heatmaps,
                  const int*   __restrict__ kp32,
                  float* __restrict__ out)
{
    const int bid = blockIdx.x;
    const int tid = threadIdx.x;
    const unsigned FULL = 0xffffffffu;

    __shared__ bool s_last;

    if (bid >= PP_BLOCKS) {
        // ---------------- det MSE partial ----------------
        const int det_bid = bid - PP_BLOCKS;
        const int plane = det_bid >> 3;                // / BLOCKS_PER_PLANE
        const int chunk = det_bid & (BLOCKS_PER_PLANE - 1);
        const int b = plane / NPARTS;
        const int p = plane % NPARTS;
        const int hw = chunk * (NTHREADS * 4) + tid * 4;   // 512*4 = 2048 elems/chunk

        const float4 m4 = *reinterpret_cast<const float4*>(masks    + (size_t)b * HW + hw);
        const float4 h4 = *reinterpret_cast<const float4*>(heatmaps + ((size_t)b * NPARTS + p) * HW + hw);

        float acc = 0.0f;
#pragma unroll
        for (int s = 0; s < SI; s++) {
            const float4 p4 = *reinterpret_cast<const float4*>(
                preds + (((size_t)(b * SI + s) * CCH + p) * HW + hw));
            const float dx = p4.x - h4.x;
            const float dy = p4.y - h4.y;
            const float dz = p4.z - h4.z;
            const float dw = p4.w - h4.w;
            acc += dx * dx * m4.x + dy * dy * m4.y + dz * dz * m4.z + dw * dw * m4.w;
        }

        // block reduction (16 warps)
#pragma unroll
        for (int o = 16; o > 0; o >>= 1) acc += __shfl_xor_sync(FULL, acc, o);
        __shared__ float wsum[16];
        const int wid = tid >> 5;
        if ((tid & 31) == 0) wsum[wid] = acc;
        __syncthreads();
        if (tid == 0) {
            float s = 0.0f;
#pragma unroll
            for (int w = 0; w < 16; w++) s += wsum[w];
            // pre-weighted: weight 1.0 * mean over (B,S,17,H,W)
            g_scratch[bid] = (double)s * (1.0 / ((double)BI * SI * NPARTS * HW));
        }
    } else {
        // ---------------- pull/push for one (b,s) ----------------
        const int b = bid / SI;
        const int s = bid % SI;

        __shared__ float gm[NPERS * NPARTS];   // g * vis
        __shared__ float vf[NPERS * NPARTS];   // vis as float
        __shared__ int   is64_s;

        // Detect keypoint dtype with one parallel warp pass:
        // int64 little-endian with values < 2^31 => all odd 32-bit words zero.
        if (tid < 32) {
            const int v = kp32[2 * tid + 1];   // odd words 1,3,...,63
            const unsigned nz = __ballot_sync(FULL, v != 0);
            if (tid == 0) is64_s = (nz == 0u) ? 1 : 0;
        }
        __syncthreads();
        const int is64 = is64_s;

        const float* tagbase = preds + ((size_t)(b * SI + s) * CCH + NPARTS) * HW;

        for (int i = tid; i < NPERS * NPARTS; i += NTHREADS) {
            const int p = i / NPARTS;
            const int k = i % NPARTS;
            const int e = (b * NPERS + p) * NPARTS + k;   // entry index
            int idx, visv;
            if (is64) { idx = kp32[4 * e];     visv = kp32[4 * e + 2]; }
            else      { idx = kp32[2 * e];     visv = kp32[2 * e + 1]; }
            const float v = (visv > 0) ? 1.0f : 0.0f;
            gm[i] = v * tagbase[idx];   // idx always in [0, LTAG)
            vf[i] = v;
        }
        __syncthreads();

        if (tid < 32) {
            const int p = tid;
            float cnt = 0.0f, sum = 0.0f;
            if (p < NPERS) {
#pragma unroll
                for (int k = 0; k < NPARTS; k++) {
                    cnt += vf[p * NPARTS + k];
                    sum += gm[p * NPARTS + k];
                }
            }
            const float validf = (p < NPERS && cnt > 0.0f) ? 1.0f : 0.0f;
            const float safe   = fmaxf(cnt, 1.0f);
            const float mean   = sum / safe;

            float pull_pp = 0.0f;
            if (p < NPERS) {
#pragma unroll
                for (int k = 0; k < NPARTS; k++) {
                    const float d = gm[p * NPARTS + k] - mean * vf[p * NPARTS + k];
                    pull_pp += d * d;
                }
            }
            pull_pp /= safe;   // TAG_DIM == 1

            const unsigned bal = __ballot_sync(FULL, validf > 0.0f);
            const float num = (float)__popc(bal);

            float pullv = pull_pp * validf;
#pragma unroll
            for (int o = 16; o > 0; o >>= 1) pullv += __shfl_xor_sync(FULL, pullv, o);
            const float pull_bs = pullv / (num + EPSV);

            float row = 0.0f;
            for (int q = 0; q < NPERS; q++) {
                const float mq = __shfl_sync(FULL, mean,   q);
                const float vq = __shfl_sync(FULL, validf, q);
                const float d  = mean - mq;
                row += vq * expf(-d * d);
            }
            row *= validf;
#pragma unroll
            for (int o = 16; o > 0; o >>= 1) row += __shfl_xor_sync(FULL, row, o);
            const float push_sum = row - num;
            const float push_bs  = push_sum / ((num - 1.0f) * num + EPSV) * 0.5f;

            if (tid == 0) {
                g_scratch[bid] = (double)(0.001f * (push_bs + pull_bs)) / (double)(BI * SI);
            }
        }
        __syncthreads();
    }

    // ---------- completion protocol: RELEASE-only atomic (no L1 invalidate) ----------
    // tid0's scratch store (same thread) is ordered before the counter update by
    // release semantics; the last block reads partials with __ldcg (L2-direct),
    // so no acquire / CCTL.IVALL is needed anywhere on the hot path.
    if (tid == 0) {
        unsigned prev;
        asm volatile("atom.release.gpu.global.add.u32 %0, [%1], 1;"
                     : "=r"(prev) : "l"(&g_done) : "memory");
        s_last = (prev == (unsigned)(TOTAL_BLOCKS - 1));
    }
    __syncthreads();

    if (s_last) {
        double acc = 0.0;
        // Fixed-order reduction -> deterministic regardless of which block runs it.
        for (int i = tid; i < TOTAL_BLOCKS; i += NTHREADS) {
            acc += __ldcg(&g_scratch[i]);
        }
#pragma unroll
        for (int o = 16; o > 0; o >>= 1) acc += __shfl_xor_sync(FULL, acc, o);
        __shared__ double wsum2[16];
        const int wid = tid >> 5;
        if ((tid & 31) == 0) wsum2[wid] = acc;
        __syncthreads();
        if (tid == 0) {
            double s = 0.0;
#pragma unroll
            for (int w = 0; w < 16; w++) s += wsum2[w];
            out[0] = (float)s;
            g_done = 0;   // all blocks arrived; plain store, visible next launch
        }
    }
}

extern "C" void kernel_launch(void* const* d_in, const int* in_sizes, int n_in,
                              void* d_out, int out_size)
{
    (void)out_size;
    const float* preds    = nullptr;
    const float* masks    = nullptr;
    const float* heatmaps = nullptr;
    const int*   kp       = nullptr;

    // Identify inputs by element count (defensive vs. ordering)
    for (int i = 0; i < n_in; i++) {
        switch (in_sizes[i]) {
            case BI * SI * CCH * HW:   preds    = (const float*)d_in[i]; break;  // 17825792
            case BI * HW:              masks    = (const float*)d_in[i]; break;  // 131072
            case BI * NPARTS * HW:     heatmaps = (const float*)d_in[i]; break;  // 2228224
            case BI * NPERS * NPARTS * 2: kp    = (const int*)d_in[i];   break;  // 8160
            default: break;
        }
    }
    if (!preds    && n_in > 0) preds    = (const float*)d_in[0];
    if (!masks    && n_in > 1) masks    = (const float*)d_in[1];
    if (!heatmaps && n_in > 2) heatmaps = (const float*)d_in[2];
    if (!kp       && n_in > 3) kp       = (const int*)d_in[3];

    loss_fused_kernel<<<TOTAL_BLOCKS, NTHREADS>>>(preds, masks, heatmaps, kp, (float*)d_out);
}

// round 10
// speedup vs baseline: 1.4737x; 1.0025x over previous
#include <cuda_runtime.h>
#include <math.h>

// Problem constants (fixed shapes from setup_inputs)
#define BI      8
#define SI      4
#define NPARTS  17
#define TAGD    1
#define CCH     ((1 + TAGD) * NPARTS)   // 34
#define HH      128
#define WW      128
#define HW      (HH * WW)               // 16384
#define NPERS   30
#define LTAG    (NPARTS * HW)           // 278528
#define EPSV    1e-6f

#define NTHREADS 512
// pull/push blocks FIRST (overlap their latency-bound gathers with the stream)
#define PP_BLOCKS   (BI * SI)                          // 32
// Det: one (b,p) plane = HW floats; 4 blocks/plane, 512 thr, 2 float4/thread
#define BLOCKS_PER_PLANE 4
#define DET_BLOCKS  (BI * NPARTS * BLOCKS_PER_PLANE)   // 544
#define TOTAL_BLOCKS (DET_BLOCKS + PP_BLOCKS)          // 576  (<= 148 SM * 4 CTA = single wave)

// Per-block partials + completion counter (no device-side allocation allowed)
__device__ double g_scratch[TOTAL_BLOCKS];
__device__ unsigned int g_done = 0;   // reset by the last block each call

__global__ void __launch_bounds__(NTHREADS, 4)
loss_fused_kernel(const float* __restrict__ preds,
                  const float* __restrict__ masks,
                  const float* __restrict__ heatmaps,
                  const int*   __restrict__ kp32,
                  float* __restrict__ out)
{
    const int bid = blockIdx.x;
    const int tid = threadIdx.x;
    const unsigned FULL = 0xffffffffu;

    __shared__ bool s_last;

    if (bid >= PP_BLOCKS) {
        // ---------------- det MSE partial ----------------
        const int det_bid = bid - PP_BLOCKS;
        const int plane = det_bid >> 2;                // / BLOCKS_PER_PLANE
        const int chunk = det_bid & (BLOCKS_PER_PLANE - 1);
        const int b = plane / NPARTS;
        const int p = plane % NPARTS;
        // Chunk covers 4096 elements; thread handles hw0 and hw0+2048.
        const int hw0 = chunk * 4096 + tid * 4;
        const int hw1 = hw0 + 2048;

        const float* mb = masks    + (size_t)b * HW;
        const float* hb = heatmaps + ((size_t)b * NPARTS + p) * HW;

        const float4 m4a = *reinterpret_cast<const float4*>(mb + hw0);
        const float4 m4b = *reinterpret_cast<const float4*>(mb + hw1);
        const float4 h4a = *reinterpret_cast<const float4*>(hb + hw0);
        const float4 h4b = *reinterpret_cast<const float4*>(hb + hw1);

        float acc = 0.0f;
#pragma unroll
        for (int s = 0; s < SI; s++) {
            const float* pb = preds + ((size_t)(b * SI + s) * CCH + p) * HW;
            const float4 p4a = *reinterpret_cast<const float4*>(pb + hw0);
            const float4 p4b = *reinterpret_cast<const float4*>(pb + hw1);
            {
                const float dx = p4a.x - h4a.x, dy = p4a.y - h4a.y;
                const float dz = p4a.z - h4a.z, dw = p4a.w - h4a.w;
                acc += dx * dx * m4a.x + dy * dy * m4a.y + dz * dz * m4a.z + dw * dw * m4a.w;
            }
            {
                const float dx = p4b.x - h4b.x, dy = p4b.y - h4b.y;
                const float dz = p4b.z - h4b.z, dw = p4b.w - h4b.w;
                acc += dx * dx * m4b.x + dy * dy * m4b.y + dz * dz * m4b.z + dw * dw * m4b.w;
            }
        }

        // block reduction (16 warps)
#pragma unroll
        for (int o = 16; o > 0; o >>= 1) acc += __shfl_xor_sync(FULL, acc, o);
        __shared__ float wsum[16];
        const int wid = tid >> 5;
        if ((tid & 31) == 0) wsum[wid] = acc;
        __syncthreads();
        if (tid == 0) {
            float s = 0.0f;
#pragma unroll
            for (int w = 0; w < 16; w++) s += wsum[w];
            // pre-weighted: weight 1.0 * mean over (B,S,17,H,W)
            g_scratch[bid] = (double)s * (1.0 / ((double)BI * SI * NPARTS * HW));
        }
    } else {
        // ---------------- pull/push for one (b,s) ----------------
        const int b = bid / SI;
        const int s = bid % SI;

        __shared__ float gm[NPERS * NPARTS];   // g * vis
        __shared__ float vf[NPERS * NPARTS];   // vis as float
        __shared__ int   is64_s;

        // Detect keypoint dtype with one parallel warp pass:
        // int64 little-endian with values < 2^31 => all odd 32-bit words zero.
        if (tid < 32) {
            const int v = kp32[2 * tid + 1];   // odd words 1,3,...,63
            const unsigned nz = __ballot_sync(FULL, v != 0);
            if (tid == 0) is64_s = (nz == 0u) ? 1 : 0;
        }
        __syncthreads();
        const int is64 = is64_s;

        const float* tagbase = preds + ((size_t)(b * SI + s) * CCH + NPARTS) * HW;

        for (int i = tid; i < NPERS * NPARTS; i += NTHREADS) {
            const int p = i / NPARTS;
            const int k = i % NPARTS;
            const int e = (b * NPERS + p) * NPARTS + k;   // entry index
            int idx, visv;
            if (is64) { idx = kp32[4 * e];     visv = kp32[4 * e + 2]; }
            else      { idx = kp32[2 * e];     visv = kp32[2 * e + 1]; }
            const float v = (visv > 0) ? 1.0f : 0.0f;
            gm[i] = v * tagbase[idx];   // idx always in [0, LTAG)
            vf[i] = v;
        }
        __syncthreads();

        if (tid < 32) {
            const int p = tid;
            float cnt = 0.0f, sum = 0.0f;
            if (p < NPERS) {
#pragma unroll
                for (int k = 0; k < NPARTS; k++) {
                    cnt += vf[p * NPARTS + k];
                    sum += gm[p * NPARTS + k];
                }
            }
            const float validf = (p < NPERS && cnt > 0.0f) ? 1.0f : 0.0f;
            const float safe   = fmaxf(cnt, 1.0f);
            const float mean   = sum / safe;

            float pull_pp = 0.0f;
            if (p < NPERS) {
#pragma unroll
                for (int k = 0; k < NPARTS; k++) {
                    const float d = gm[p * NPARTS + k] - mean * vf[p * NPARTS + k];
                    pull_pp += d * d;
                }
            }
            pull_pp /= safe;   // TAG_DIM == 1

            const unsigned bal = __ballot_sync(FULL, validf > 0.0f);
            const float num = (float)__popc(bal);

            float pullv = pull_pp * validf;
#pragma unroll
            for (int o = 16; o > 0; o >>= 1) pullv += __shfl_xor_sync(FULL, pullv, o);
            const float pull_bs = pullv / (num + EPSV);

            float row = 0.0f;
            for (int q = 0; q < NPERS; q++) {
                const float mq = __shfl_sync(FULL, mean,   q);
                const float vq = __shfl_sync(FULL, validf, q);
                const float d  = mean - mq;
                row += vq * expf(-d * d);
            }
            row *= validf;
#pragma unroll
            for (int o = 16; o > 0; o >>= 1) row += __shfl_xor_sync(FULL, row, o);
            const float push_sum = row - num;
            const float push_bs  = push_sum / ((num - 1.0f) * num + EPSV) * 0.5f;

            if (tid == 0) {
                g_scratch[bid] = (double)(0.001f * (push_bs + pull_bs)) / (double)(BI * SI);
            }
        }
        __syncthreads();
    }

    // ---------- completion protocol: RELEASE-only atomic (no L1 invalidate) ----------
    // tid0's scratch store (same thread) is ordered before the counter update by
    // release semantics; the last block reads partials with __ldcg (L2-direct),
    // so no acquire / CCTL.IVALL is needed anywhere on the hot path.
    if (tid == 0) {
        unsigned prev;
        asm volatile("atom.release.gpu.global.add.u32 %0, [%1], 1;"
                     : "=r"(prev) : "l"(&g_done) : "memory");
        s_last = (prev == (unsigned)(TOTAL_BLOCKS - 1));
    }
    __syncthreads();

    if (s_last) {
        double acc = 0.0;
        // Fixed-order reduction -> deterministic regardless of which block runs it.
        for (int i = tid; i < TOTAL_BLOCKS; i += NTHREADS) {
            acc += __ldcg(&g_scratch[i]);
        }
#pragma unroll
        for (int o = 16; o > 0; o >>= 1) acc += __shfl_xor_sync(FULL, acc, o);
        __shared__ double wsum2[16];
        const int wid = tid >> 5;
        if ((tid & 31) == 0) wsum2[wid] = acc;
        __syncthreads();
        if (tid == 0) {
            double s = 0.0;
#pragma unroll
            for (int w = 0; w < 16; w++) s += wsum2[w];
            out[0] = (float)s;
            g_done = 0;   // all blocks arrived; plain store, visible next launch
        }
    }
}

extern "C" void kernel_launch(void* const* d_in, const int* in_sizes, int n_in,
                              void* d_out, int out_size)
{
    (void)out_size;
    const float* preds    = nullptr;
    const float* masks    = nullptr;
    const float* heatmaps = nullptr;
    const int*   kp       = nullptr;

    // Identify inputs by element count (defensive vs. ordering)
    for (int i = 0; i < n_in; i++) {
        switch (in_sizes[i]) {
            case BI * SI * CCH * HW:   preds    = (const float*)d_in[i]; break;  // 17825792
            case BI * HW:              masks    = (const float*)d_in[i]; break;  // 131072
            case BI * NPARTS * HW:     heatmaps = (const float*)d_in[i]; break;  // 2228224
            case BI * NPERS * NPARTS * 2: kp    = (const int*)d_in[i];   break;  // 8160
            default: break;
        }
    }
    if (!preds    && n_in > 0) preds    = (const float*)d_in[0];
    if (!masks    && n_in > 1) masks    = (const float*)d_in[1];
    if (!heatmaps && n_in > 2) heatmaps = (const float*)d_in[2];
    if (!kp       && n_in > 3) kp       = (const int*)d_in[3];

    loss_fused_kernel<<<TOTAL_BLOCKS, NTHREADS>>>(preds, masks, heatmaps, kp, (float*)d_out);
}